// round 12
// baseline (speedup 1.0000x reference)
#include <cuda_runtime.h>
#include <math.h>
#include <stdint.h>

// Problem constants (fixed shapes)
#define BB 2
#define SS 2048
#define DD 2048
#define HH 32
#define GG 8
#define HD 64
#define KVD 512        // G*HD
#define MTOT (BB*SS)   // 4096

// Scratch (static device globals; no allocation allowed)
__device__ uint32_t g_q  [MTOT*DD];    // Q proj: tf32 bits, paired word order
__device__ uint32_t g_k  [MTOT*KVD];   // K proj: tf32 bits, paired word order
__device__ uint32_t g_v  [MTOT*KVD];   // V proj: tf32 bits, natural order
__device__ float    g_ao [MTOT*DD];    // attention out: tf32 bits, paired rows
__device__ uint32_t g_xp [MTOT*DD];    // x,  tf32 + paired rows
__device__ uint32_t g_kvp[MTOT*DD];    // kv, tf32 + paired rows
__device__ uint32_t g_wqp[DD*DD];      // weights: tf32, pair-row interleaved
__device__ uint32_t g_wkp[DD*KVD];
__device__ uint32_t g_wvp[DD*KVD];
__device__ uint32_t g_wop[DD*DD];

// ---------------------------------------------------------------------------
// helpers
// ---------------------------------------------------------------------------
__device__ __forceinline__ uint32_t f2tf(float x) {
    uint32_t r;
    asm("cvt.rna.tf32.f32 %0, %1;" : "=r"(r) : "f"(x));
    return r;
}
__device__ __forceinline__ uint32_t sptr(const void* p) {
    return (uint32_t)__cvta_generic_to_shared(p);
}
__device__ __forceinline__ void cpa16(uint32_t s, const void* g) {
    asm volatile("cp.async.cg.shared.global [%0], [%1], 16;" :: "r"(s), "l"(g));
}
#define CP_COMMIT() asm volatile("cp.async.commit_group;")
#define CP_WAIT(N)  asm volatile("cp.async.wait_group %0;" :: "n"(N))

__device__ __forceinline__ void mma_tf32(
    float& c0, float& c1, float& c2, float& c3,
    uint32_t a0, uint32_t a1, uint32_t a2, uint32_t a3,
    uint32_t b0, uint32_t b1)
{
    asm volatile(
        "mma.sync.aligned.m16n8k8.row.col.f32.tf32.tf32.f32 "
        "{%0,%1,%2,%3}, {%4,%5,%6,%7}, {%8,%9}, {%0,%1,%2,%3};"
        : "+f"(c0), "+f"(c1), "+f"(c2), "+f"(c3)
        : "r"(a0), "r"(a1), "r"(a2), "r"(a3), "r"(b0), "r"(b1));
}
__device__ __forceinline__ void mma_tf32v(float c[4], const uint32_t a[4],
                                          uint32_t b0, uint32_t b1)
{
    mma_tf32(c[0], c[1], c[2], c[3], a[0], a[1], a[2], a[3], b0, b1);
}

// ---------------------------------------------------------------------------
// Fused pre-pass (bit-identical conversions)
// ---------------------------------------------------------------------------
__device__ __forceinline__ void do_pair_rows(
    const float4* __restrict__ in, uint4* __restrict__ out, int idx)
{
    const float4 v0 = in[idx * 2];
    const float4 v1 = in[idx * 2 + 1];
    out[idx * 2]     = make_uint4(f2tf(v0.x), f2tf(v1.x), f2tf(v0.y), f2tf(v1.y));
    out[idx * 2 + 1] = make_uint4(f2tf(v0.z), f2tf(v1.z), f2tf(v0.w), f2tf(v1.w));
}

__device__ __forceinline__ void do_pair_weights(
    const float* __restrict__ W, uint32_t* __restrict__ Wp, int N, int idx)
{
    const int ncq = N >> 2;
    const int p   = idx / ncq;
    const int nc  = idx - p * ncq;
    const int klo = (p >> 2) * 8 + (p & 3);
    const float4 lo = *(const float4*)(W + (size_t)klo * N + nc * 4);
    const float4 hi = *(const float4*)(W + (size_t)(klo + 4) * N + nc * 4);
    uint4* op = (uint4*)(Wp + (size_t)p * (2 * N) + nc * 8);
    op[0] = make_uint4(f2tf(lo.x), f2tf(hi.x), f2tf(lo.y), f2tf(hi.y));
    op[1] = make_uint4(f2tf(lo.z), f2tf(hi.z), f2tf(lo.w), f2tf(hi.w));
}

#define PB_X   4096
#define PB_KV  (PB_X  + 4096)
#define PB_WQ  (PB_KV + 2048)
#define PB_WK  (PB_WQ + 512)
#define PB_WV  (PB_WK + 512)
#define PB_WO  (PB_WV + 2048)   // total 13312 blocks

__global__ void __launch_bounds__(256) prepass_kernel(
    const float* __restrict__ x,  const float* __restrict__ kv,
    const float* __restrict__ Wq, const float* __restrict__ Wk,
    const float* __restrict__ Wv, const float* __restrict__ Wo,
    uint32_t* __restrict__ xp, uint32_t* __restrict__ kvp,
    uint32_t* __restrict__ wqp, uint32_t* __restrict__ wkp,
    uint32_t* __restrict__ wvp, uint32_t* __restrict__ wop)
{
    const int blk = blockIdx.x;
    if (blk < PB_X) {
        do_pair_rows((const float4*)x, (uint4*)xp, blk * 256 + threadIdx.x);
    } else if (blk < PB_KV) {
        do_pair_rows((const float4*)kv, (uint4*)kvp,
                     (blk - PB_X) * 256 + threadIdx.x);
    } else if (blk < PB_WQ) {
        do_pair_weights(Wq, wqp, DD,  (blk - PB_KV) * 256 + threadIdx.x);
    } else if (blk < PB_WK) {
        do_pair_weights(Wk, wkp, KVD, (blk - PB_WQ) * 256 + threadIdx.x);
    } else if (blk < PB_WV) {
        do_pair_weights(Wv, wvp, KVD, (blk - PB_WK) * 256 + threadIdx.x);
    } else {
        do_pair_weights(Wo, wop, DD,  (blk - PB_WV) * 256 + threadIdx.x);
    }
}

// ---------------------------------------------------------------------------
// TF32 GEMM + bias, 128x256x32 tile, 512 threads (16 warps, warp tile 64x32),
// 2 CTAs/SM, cp.async double buffer, single __syncthreads per K-chunk.
// Epilogue: EM=0 fp32 natural | EM=1 tf32 paired | EM=2 tf32 natural.
// Accumulation order identical to the 128x128 version -> bit-identical result.
// ---------------------------------------------------------------------------
#define ASP 40                       // A row stride (32 + 8 pad)
#define BSP 520                      // B pair-row stride (512 + 8 pad)
#define GEMM_BUF_WORDS (128*ASP + 16*BSP)          // 13440 words
#define GEMM_SMEM_BYTES (2 * GEMM_BUF_WORDS * 4)   // 107520 B

#define GSTAGE(asb, bsb, ktc) do {                                          \
    const int _kb = (ktc) << 5;                                             \
    const int _pg = (ktc) << 4;                                             \
    _Pragma("unroll")                                                       \
    for (int _it = 0; _it < 2; _it++) {                                     \
        int _idx = _it * 512 + tid;                                         \
        int _r = _idx >> 3, _w = (_idx & 7) << 2;                           \
        cpa16(sptr((asb) + _r * ASP + _w),                                  \
              Ap + (size_t)(row0 + _r) * K + _kb + _w);                     \
    }                                                                       \
    _Pragma("unroll")                                                       \
    for (int _it = 0; _it < 4; _it++) {                                     \
        int _idx = _it * 512 + tid;                                         \
        int _pr = _idx >> 7, _w = (_idx & 127) << 2;                        \
        cpa16(sptr((bsb) + _pr * BSP + _w),                                 \
              Wp + (size_t)(_pg + _pr) * wrow + col0 * 2 + _w);             \
    }                                                                       \
} while(0)

template<int EM>
__device__ __forceinline__ void gemm_body(
    const uint32_t* __restrict__ Ap, const uint32_t* __restrict__ Wp,
    const float* __restrict__ bias, void* __restrict__ C,
    int N, int K, int row0, int col0, uint32_t* sm)
{
    uint32_t* As0 = sm;
    uint32_t* Bs0 = As0 + 128 * ASP;
    uint32_t* As1 = Bs0 + 16 * BSP;
    uint32_t* Bs1 = As1 + 128 * ASP;

    const int tid  = threadIdx.x;
    const int lane = tid & 31;
    const int warp = tid >> 5;        // 0..15
    const int g    = lane >> 2;
    const int tig  = lane & 3;
    const int warpM = warp >> 3;      // 0..1  (64 rows each)
    const int warpN = warp & 7;       // 0..7  (32 cols each)

    float c[4][4][4];
    #pragma unroll
    for (int i = 0; i < 4; i++)
        #pragma unroll
        for (int j = 0; j < 4; j++)
            #pragma unroll
            for (int r = 0; r < 4; r++) c[i][j][r] = 0.0f;

    const int nk = K >> 5;
    const size_t wrow = (size_t)(2 * N);

    GSTAGE(As0, Bs0, 0);
    CP_COMMIT();

    for (int kt = 0; kt < nk; kt++) {
        CP_WAIT(0);
        __syncthreads();   // chunk kt visible; all warps done reading other buf

        if (kt + 1 < nk) {
            if ((kt + 1) & 1) GSTAGE(As1, Bs1, kt + 1);
            else              GSTAGE(As0, Bs0, kt + 1);
            CP_COMMIT();
        }

        const uint32_t* as = (kt & 1) ? As1 : As0;
        const uint32_t* bs = (kt & 1) ? Bs1 : Bs0;

        #pragma unroll
        for (int ks = 0; ks < 4; ks++) {
            uint32_t af[4][4];
            #pragma unroll
            for (int mt = 0; mt < 4; mt++) {
                const uint32_t* ap = as + (warpM * 64 + mt * 16 + g) * ASP
                                        + ks * 8 + 2 * tig;
                uint2 u0 = *(const uint2*)ap;
                uint2 u8 = *(const uint2*)(ap + 8 * ASP);
                af[mt][0] = u0.x; af[mt][1] = u8.x;
                af[mt][2] = u0.y; af[mt][3] = u8.y;
            }
            uint2 bf[4];
            #pragma unroll
            for (int nt = 0; nt < 4; nt++)
                bf[nt] = *(const uint2*)(bs + (ks * 4 + tig) * BSP
                                            + (warpN * 32 + nt * 8 + g) * 2);
            #pragma unroll
            for (int mt = 0; mt < 4; mt++)
                #pragma unroll
                for (int nt = 0; nt < 4; nt++)
                    mma_tf32v(c[mt][nt], af[mt], bf[nt].x, bf[nt].y);
        }
    }

    const int w0p = 4 * (tig & 1) + (tig >> 1);
    #pragma unroll
    for (int mt = 0; mt < 4; mt++) {
        const int r = row0 + warpM * 64 + mt * 16 + g;
        #pragma unroll
        for (int nt = 0; nt < 4; nt++) {
            const int cb = col0 + warpN * 32 + nt * 8;
            const float bv0 = bias[cb + 2 * tig];
            const float bv1 = bias[cb + 2 * tig + 1];
            if (EM == 0) {
                float* Cp = (float*)C;
                *(float2*)(Cp + (size_t)r * N + cb + 2 * tig) =
                    make_float2(c[mt][nt][0] + bv0, c[mt][nt][1] + bv1);
                *(float2*)(Cp + (size_t)(r + 8) * N + cb + 2 * tig) =
                    make_float2(c[mt][nt][2] + bv0, c[mt][nt][3] + bv1);
            } else if (EM == 1) {
                uint32_t* p0 = (uint32_t*)C + (size_t)r * N + cb;
                uint32_t* p8 = (uint32_t*)C + (size_t)(r + 8) * N + cb;
                p0[w0p]     = f2tf(c[mt][nt][0] + bv0);
                p0[w0p + 2] = f2tf(c[mt][nt][1] + bv1);
                p8[w0p]     = f2tf(c[mt][nt][2] + bv0);
                p8[w0p + 2] = f2tf(c[mt][nt][3] + bv1);
            } else {
                uint32_t* p0 = (uint32_t*)C + (size_t)r * N + cb + 2 * tig;
                uint32_t* p8 = (uint32_t*)C + (size_t)(r + 8) * N + cb + 2 * tig;
                *(uint2*)p0 = make_uint2(f2tf(c[mt][nt][0] + bv0),
                                         f2tf(c[mt][nt][1] + bv1));
                *(uint2*)p8 = make_uint2(f2tf(c[mt][nt][2] + bv0),
                                         f2tf(c[mt][nt][3] + bv1));
            }
        }
    }
}

__global__ void __launch_bounds__(512, 2) gemm_out_kernel(
    const uint32_t* __restrict__ Ap, const uint32_t* __restrict__ Wp,
    const float* __restrict__ bias, float* __restrict__ C, int N, int K)
{
    extern __shared__ uint32_t sm[];
    gemm_body<0>(Ap, Wp, bias, C, N, K, blockIdx.y * 128, blockIdx.x * 256, sm);
}

// Fused Q+K+V projections: grid.x = 12 (8 Q cols, 2 K, 2 V), 256-col tiles.
__global__ void __launch_bounds__(512, 2) gemm_qkv_kernel(
    const uint32_t* __restrict__ xp,  const uint32_t* __restrict__ kvp,
    const uint32_t* __restrict__ wqp, const float* __restrict__ bq, uint32_t* __restrict__ q,
    const uint32_t* __restrict__ wkp, const float* __restrict__ bk, uint32_t* __restrict__ k,
    const uint32_t* __restrict__ wvp, const float* __restrict__ bv, uint32_t* __restrict__ v)
{
    extern __shared__ uint32_t sm[];
    const int bx = blockIdx.x;
    const int row0 = blockIdx.y * 128;
    if (bx < 8)
        gemm_body<1>(xp,  wqp, bq, q, DD,  DD, row0, bx * 256, sm);
    else if (bx < 10)
        gemm_body<1>(kvp, wkp, bk, k, KVD, DD, row0, (bx - 8) * 256, sm);
    else
        gemm_body<2>(kvp, wvp, bv, v, KVD, DD, row0, (bx - 10) * 256, sm);
}

// ---------------------------------------------------------------------------
// Fused causal GQA flash attention, TF32 MMA (unchanged from R8/R9).
// 256 threads (8 warps x 16 q-rows), 128-row q-blocks, cp.async staging.
// ---------------------------------------------------------------------------
#define KST 72
#define VST 72
#define QST 72
#define PST 68
#define ATTN_SMEM_WORDS (64*KST + 64*VST + 128*QST + 128*PST)
#define ATTN_SMEM_BYTES (ATTN_SMEM_WORDS * 4)

__global__ void __launch_bounds__(256, 2) attn_tf32_kernel(
    const uint32_t* __restrict__ Q, const uint32_t* __restrict__ Kg,
    const uint32_t* __restrict__ Vg, float* __restrict__ O)
{
    extern __shared__ uint32_t smu[];
    uint32_t* Ks = smu;
    uint32_t* Vs = Ks + 64 * KST;
    uint32_t* Qs = Vs + 64 * VST;
    uint32_t* Ps = Qs + 128 * QST;

    const int tid  = threadIdx.x;
    const int lane = tid & 31;
    const int warp = tid >> 5;
    const int g    = lane >> 2;
    const int tig  = lane & 3;
    const int wr   = warp * 16;

    const int pr = blockIdx.x;
    const int bh = blockIdx.y;
    const int b  = bh >> 5;
    const int h  = bh & 31;
    const int grp = h >> 2;

    const uint32_t* Qb = Q  + (size_t)(b * SS) * DD  + h * HD;
    const uint32_t* Kb = Kg + (size_t)(b * SS) * KVD + grp * HD;
    const uint32_t* Vb = Vg + (size_t)(b * SS) * KVD + grp * HD;

    for (int halfp = 0; halfp < 2; halfp++) {
        const int Qi = halfp ? (15 - pr) : pr;
        const int q0 = Qi * 128;

        __syncthreads();

        #pragma unroll
        for (int it = 0; it < 8; it++) {
            int idx = it * 256 + tid;
            int r = idx >> 4, c = (idx & 15) << 2;
            cpa16(sptr(Qs + r * QST + c), Qb + (size_t)(q0 + r) * DD + c);
        }
        CP_COMMIT();

        float o[8][4];
        float m0 = -1e30f, m1 = -1e30f, l0 = 0.0f, l1 = 0.0f;
        #pragma unroll
        for (int nt = 0; nt < 8; nt++)
            #pragma unroll
            for (int i = 0; i < 4; i++) o[nt][i] = 0.0f;

        const int tmax = 2 * Qi + 1;
        for (int t = 0; t <= tmax; t++) {
            const int k0 = t * 64;
            __syncthreads();

            #pragma unroll
            for (int it = 0; it < 4; it++) {
                int idx = it * 256 + tid;
                int r = idx >> 4, c = (idx & 15) << 2;
                cpa16(sptr(Ks + r * KST + c), Kb + (size_t)(k0 + r) * KVD + c);
            }
            #pragma unroll
            for (int it = 0; it < 4; it++) {
                int idx = it * 256 + tid;
                int r = idx >> 4, c = (idx & 15) << 2;
                cpa16(sptr(Vs + r * VST + c), Vb + (size_t)(k0 + r) * KVD + c);
            }
            CP_COMMIT();
            CP_WAIT(0);
            __syncthreads();

            float s[8][4];
            #pragma unroll
            for (int nt = 0; nt < 8; nt++)
                #pragma unroll
                for (int i = 0; i < 4; i++) s[nt][i] = 0.0f;

            #pragma unroll
            for (int ks = 0; ks < 8; ks++) {
                const uint32_t* qp = Qs + (wr + g) * QST + ks * 8 + 2 * tig;
                uint2 u0 = *(const uint2*)qp;
                uint2 u8 = *(const uint2*)(qp + 8 * QST);
                uint32_t af[4] = {u0.x, u8.x, u0.y, u8.y};
                #pragma unroll
                for (int nt = 0; nt < 8; nt++) {
                    uint2 kb = *(const uint2*)(Ks + (nt * 8 + g) * KST + ks * 8 + 2 * tig);
                    mma_tf32v(s[nt], af, kb.x, kb.y);
                }
            }

            const bool needmask = (k0 + 63 > q0 + wr);
            const int rowg = q0 + wr + g;
            #pragma unroll
            for (int nt = 0; nt < 8; nt++) {
                const int cbase = k0 + nt * 8 + 2 * tig;
                #pragma unroll
                for (int i = 0; i < 4; i++) {
                    float v = s[nt][i] * 0.125f;
                    if (needmask) {
                        int col = cbase + (i & 1);
                        int row = rowg + ((i & 2) ? 8 : 0);
                        if (col > row) v = -1e30f;
                    }
                    s[nt][i] = v;
                }
            }

            float r0 = -1e30f, r1 = -1e30f;
            #pragma unroll
            for (int nt = 0; nt < 8; nt++) {
                r0 = fmaxf(r0, fmaxf(s[nt][0], s[nt][1]));
                r1 = fmaxf(r1, fmaxf(s[nt][2], s[nt][3]));
            }
            r0 = fmaxf(r0, __shfl_xor_sync(0xffffffffu, r0, 1));
            r0 = fmaxf(r0, __shfl_xor_sync(0xffffffffu, r0, 2));
            r1 = fmaxf(r1, __shfl_xor_sync(0xffffffffu, r1, 1));
            r1 = fmaxf(r1, __shfl_xor_sync(0xffffffffu, r1, 2));

            const float mn0 = fmaxf(m0, r0), mn1 = fmaxf(m1, r1);
            const float e0 = __expf(m0 - mn0), e1 = __expf(m1 - mn1);
            m0 = mn0; m1 = mn1;

            float ls0 = 0.0f, ls1 = 0.0f;
            uint32_t* pbase = Ps + (wr + g) * PST;
            #pragma unroll
            for (int nt = 0; nt < 8; nt++) {
                o[nt][0] *= e0; o[nt][1] *= e0;
                o[nt][2] *= e1; o[nt][3] *= e1;
                float p0 = __expf(s[nt][0] - mn0);
                float p1 = __expf(s[nt][1] - mn0);
                float p2 = __expf(s[nt][2] - mn1);
                float p3 = __expf(s[nt][3] - mn1);
                ls0 += p0 + p1; ls1 += p2 + p3;
                uint32_t* pp = pbase + nt * 8 + 2 * tig;
                *(uint2*)pp             = make_uint2(f2tf(p0), f2tf(p1));
                *(uint2*)(pp + 8 * PST) = make_uint2(f2tf(p2), f2tf(p3));
            }
            ls0 += __shfl_xor_sync(0xffffffffu, ls0, 1);
            ls0 += __shfl_xor_sync(0xffffffffu, ls0, 2);
            ls1 += __shfl_xor_sync(0xffffffffu, ls1, 1);
            ls1 += __shfl_xor_sync(0xffffffffu, ls1, 2);
            l0 = l0 * e0 + ls0;
            l1 = l1 * e1 + ls1;

            __syncwarp();

            #pragma unroll
            for (int ks = 0; ks < 8; ks++) {
                const uint32_t* pp = Ps + (wr + g) * PST + ks * 8 + tig;
                uint32_t pa[4];
                pa[0] = pp[0];
                pa[1] = pp[8 * PST];
                pa[2] = pp[4];
                pa[3] = pp[8 * PST + 4];
                #pragma unroll
                for (int nt = 0; nt < 8; nt++) {
                    const uint32_t* vp = Vs + (ks * 8 + tig) * VST + nt * 8 + g;
                    mma_tf32v(o[nt], pa, vp[0], vp[4 * VST]);
                }
            }
        }

        const int w0 = 4 * (tig & 1) + (tig >> 1);
        const float inv0 = 1.0f / l0, inv1 = 1.0f / l1;
        float* Ob = O + (size_t)(b * SS + q0 + wr + g) * DD + h * HD;
        #pragma unroll
        for (int nt = 0; nt < 8; nt++) {
            float* p0 = Ob + nt * 8;
            float* p8 = Ob + 8 * DD + nt * 8;
            p0[w0]     = __uint_as_float(f2tf(o[nt][0] * inv0));
            p0[w0 + 2] = __uint_as_float(f2tf(o[nt][1] * inv0));
            p8[w0]     = __uint_as_float(f2tf(o[nt][2] * inv1));
            p8[w0 + 2] = __uint_as_float(f2tf(o[nt][3] * inv1));
        }
    }
}

// ---------------------------------------------------------------------------
// Launch
// ---------------------------------------------------------------------------
extern "C" void kernel_launch(void* const* d_in, const int* in_sizes, int n_in,
                              void* d_out, int out_size)
{
    (void)in_sizes; (void)n_in; (void)out_size;
    const float* x  = (const float*)d_in[0];
    const float* kv = (const float*)d_in[1];
    const float* Wq = (const float*)d_in[2];
    const float* bq = (const float*)d_in[3];
    const float* Wk = (const float*)d_in[4];
    const float* bk = (const float*)d_in[5];
    const float* Wv = (const float*)d_in[6];
    const float* bv = (const float*)d_in[7];
    const float* Wo = (const float*)d_in[8];
    const float* bo = (const float*)d_in[9];
    float* out = (float*)d_out;

    uint32_t *q, *k, *v, *xp, *kvp, *wqp, *wkp, *wvp, *wop;
    float* ao;
    cudaGetSymbolAddress((void**)&q,   g_q);
    cudaGetSymbolAddress((void**)&k,   g_k);
    cudaGetSymbolAddress((void**)&v,   g_v);
    cudaGetSymbolAddress((void**)&ao,  g_ao);
    cudaGetSymbolAddress((void**)&xp,  g_xp);
    cudaGetSymbolAddress((void**)&kvp, g_kvp);
    cudaGetSymbolAddress((void**)&wqp, g_wqp);
    cudaGetSymbolAddress((void**)&wkp, g_wkp);
    cudaGetSymbolAddress((void**)&wvp, g_wvp);
    cudaGetSymbolAddress((void**)&wop, g_wop);

    cudaFuncSetAttribute(gemm_out_kernel,
                         cudaFuncAttributeMaxDynamicSharedMemorySize,
                         GEMM_SMEM_BYTES);
    cudaFuncSetAttribute(gemm_qkv_kernel,
                         cudaFuncAttributeMaxDynamicSharedMemorySize,
                         GEMM_SMEM_BYTES);
    cudaFuncSetAttribute(attn_tf32_kernel,
                         cudaFuncAttributeMaxDynamicSharedMemorySize,
                         ATTN_SMEM_BYTES);

    // single fused pre-pass (all tf32 conversions + re-layouts)
    prepass_kernel<<<PB_WO, 256>>>(x, kv, Wq, Wk, Wv, Wo,
                                   xp, kvp, wqp, wkp, wvp, wop);

    // fused Q+K+V projections -> tf32 outputs (Q/K paired, V natural)
    gemm_qkv_kernel<<<dim3(12, MTOT / 128), 512, GEMM_SMEM_BYTES>>>(
        xp, kvp, wqp, bq, q, wkp, bk, k, wvp, bv, v);

    // fused causal GQA attention
    attn_tf32_kernel<<<dim3(8, BB * HH), 256, ATTN_SMEM_BYTES>>>(q, k, v, ao);

    // output projection (consumes pre-paired tf32 ao directly; one wave)
    gemm_out_kernel<<<dim3(DD / 256, MTOT / 128), 512, GEMM_SMEM_BYTES>>>(
        (const uint32_t*)ao, wop, bo, out, DD, DD);
}